// round 17
// baseline (speedup 1.0000x reference)
#include <cuda_runtime.h>
#include <cuda_fp16.h>

#define BB 2
#define LL 512
#define DD 128
#define D2 64         // half2 pairs along d
#define TI 16
#define TJ 64
#define TJP 65
#define PRT 16        // proj rows per block
#define SR 8          // softmax rows per block

__device__ unsigned g_sW_h2[BB*LL*D2];   // half2-packed sW
__device__ unsigned g_hU_h2[BB*LL*D2];   // half2-packed hU
__device__ float    g_scores[(size_t)BB*LL*LL];

__device__ __forceinline__ __half2 h2tanh_apx(__half2 x){
    unsigned r, xi = *reinterpret_cast<unsigned*>(&x);
    asm("tanh.approx.f16x2 %0, %1;" : "=r"(r) : "r"(xi));
    return *reinterpret_cast<__half2*>(&r);
}
__device__ __forceinline__ unsigned pack_h2(float lo, float hi){
    __half2 hh = __floats2half2_rn(lo, hi);
    return *reinterpret_cast<unsigned*>(&hh);
}

// ---- Kernel 0: sW = s@W, hU = h@U. 256 thr, 16 rows, warp-broadcast M mapping ----
__global__ void __launch_bounds__(256) proj_kernel(const float* __restrict__ s,
                                                   const float* __restrict__ h,
                                                   const float* __restrict__ W,
                                                   const float* __restrict__ U){
    __shared__ float M_s[64][DD];     // 32KB k-tile of weights
    __shared__ float rs_t[DD][PRT];   // 8KB transposed input rows
    int rt    = blockIdx.x;
    int which = blockIdx.y;
    const float* src = which ? h : s;
    const float* M   = which ? U : W;
    unsigned* dst    = which ? g_hU_h2 : g_sW_h2;
    int t = threadIdx.x;
    int row0 = rt * PRT;

    // load 16 rows transposed (coalesced float4 reads, scattered smem writes)
    {
        const float4* sp = (const float4*)(src + (size_t)row0*DD);
#pragma unroll
        for (int q = 0; q < 2; q++){
            int idx = t + q*256;        // over 512 float4
            int row = idx >> 5;         // 32 float4 per row
            int k4  = idx & 31;
            float4 v4 = sp[idx];
            rs_t[k4*4+0][row] = v4.x;
            rs_t[k4*4+1][row] = v4.y;
            rs_t[k4*4+2][row] = v4.z;
            rs_t[k4*4+3][row] = v4.w;
        }
    }

    // mapping: 8 lanes share one M address -> intra-warp broadcast dedup
    int d4 = t >> 3;     // 0..31 float4 column of M (4 distinct per warp)
    int rg = t & 7;      // 0..7 -> rows 2rg, 2rg+1
    float4 acc0 = make_float4(0.f,0.f,0.f,0.f);
    float4 acc1 = make_float4(0.f,0.f,0.f,0.f);

    for (int kt = 0; kt < 2; ++kt){
        __syncthreads();
        // stage M k-tile 64x128 (coalesced copy)
        const float4* mp = (const float4*)(M + (size_t)kt*64*DD);
        float4* md = (float4*)&M_s[0][0];
#pragma unroll
        for (int q = 0; q < 8; q++) md[t + q*256] = mp[t + q*256];
        __syncthreads();

#pragma unroll 4
        for (int kk = 0; kk < 64; ++kk){
            float4 m = ((const float4*)&M_s[kk][0])[d4];          // 64B/warp, ~1wf
            float2 a = *(const float2*)&rs_t[kt*64 + kk][rg*2];   // 64B/warp, bcast
            acc0.x = fmaf(a.x, m.x, acc0.x);
            acc0.y = fmaf(a.x, m.y, acc0.y);
            acc0.z = fmaf(a.x, m.z, acc0.z);
            acc0.w = fmaf(a.x, m.w, acc0.w);
            acc1.x = fmaf(a.y, m.x, acc1.x);
            acc1.y = fmaf(a.y, m.y, acc1.y);
            acc1.z = fmaf(a.y, m.z, acc1.z);
            acc1.w = fmaf(a.y, m.w, acc1.w);
        }
    }

    // store half2-packed (uint2 per row)
    unsigned* dp = dst + (size_t)(row0 + rg*2)*D2 + d4*2;
    uint2 u0, u1;
    u0.x = pack_h2(acc0.x, acc0.y);  u0.y = pack_h2(acc0.z, acc0.w);
    u1.x = pack_h2(acc1.x, acc1.y);  u1.y = pack_h2(acc1.z, acc1.w);
    *(uint2*)dp        = u0;
    *(uint2*)(dp + D2) = u1;
}

// ---------------- Kernel 1: scores, packed half2 pipeline (at MUFU floor) ----------------
__global__ void __launch_bounds__(256) scores_kernel(const float* __restrict__ v){
    __shared__ __half2 hU_h2[D2][TJP];
    __shared__ __half2 sW_h2[TI][D2];
    __shared__ __half2 v_h2[D2];

    int b  = blockIdx.z;
    int i0 = blockIdx.y * TI;
    int j0 = blockIdx.x * TJ;
    int t  = threadIdx.x;

    if (t < D2){
        float2 vv = ((const float2*)v)[t];
        v_h2[t] = __floats2half2_rn(vv.x, vv.y);
    }
    {   // sW tile: 512 uint2, direct copy
        const uint2* srcw = (const uint2*)(g_sW_h2 + (size_t)(b*LL + i0)*D2);
#pragma unroll
        for (int q = 0; q < 2; q++){
            int lin = t + q*256;
            int i  = lin >> 5;
            int du = lin & 31;
            ((uint2*)&sW_h2[i][0])[du] = srcw[lin];
        }
    }
    {   // hU tile transposed: 4096 uint scalar
        const unsigned* srcu = g_hU_h2 + (size_t)(b*LL + j0)*D2;
#pragma unroll
        for (int q = 0; q < 16; q++){
            int lin = t + q*256;
            int j  = lin >> 6;
            int d2 = lin & 63;
            *(unsigned*)&hU_h2[d2][j] = srcu[lin];
        }
    }
    __syncthreads();

    int jl = t & 63;
    int ib = (t >> 6) * 4;

    float2 f0 = make_float2(0.f,0.f), f1 = f0, f2 = f0, f3 = f0;
    const __half2* w0p = &sW_h2[ib+0][0];
    const __half2* w1p = &sW_h2[ib+1][0];
    const __half2* w2p = &sW_h2[ib+2][0];
    const __half2* w3p = &sW_h2[ib+3][0];
    const __half2 hz = __floats2half2_rn(0.f, 0.f);

#pragma unroll
    for (int gg = 0; gg < 8; ++gg){
        __half2 a0 = hz, a1 = hz, a2 = hz, a3 = hz;
#pragma unroll
        for (int g2 = 0; g2 < 2; ++g2){
            int g = gg*2 + g2;
            __half2 hu0 = hU_h2[4*g+0][jl];
            __half2 hu1 = hU_h2[4*g+1][jl];
            __half2 hu2 = hU_h2[4*g+2][jl];
            __half2 hu3 = hU_h2[4*g+3][jl];
            __half2 vv0 = v_h2[4*g+0];
            __half2 vv1 = v_h2[4*g+1];
            __half2 vv2 = v_h2[4*g+2];
            __half2 vv3 = v_h2[4*g+3];

            a0 = __hfma2(h2tanh_apx(__hadd2(w0p[4*g+0], hu0)), vv0, a0);
            a0 = __hfma2(h2tanh_apx(__hadd2(w0p[4*g+1], hu1)), vv1, a0);
            a0 = __hfma2(h2tanh_apx(__hadd2(w0p[4*g+2], hu2)), vv2, a0);
            a0 = __hfma2(h2tanh_apx(__hadd2(w0p[4*g+3], hu3)), vv3, a0);

            a1 = __hfma2(h2tanh_apx(__hadd2(w1p[4*g+0], hu0)), vv0, a1);
            a1 = __hfma2(h2tanh_apx(__hadd2(w1p[4*g+1], hu1)), vv1, a1);
            a1 = __hfma2(h2tanh_apx(__hadd2(w1p[4*g+2], hu2)), vv2, a1);
            a1 = __hfma2(h2tanh_apx(__hadd2(w1p[4*g+3], hu3)), vv3, a1);

            a2 = __hfma2(h2tanh_apx(__hadd2(w2p[4*g+0], hu0)), vv0, a2);
            a2 = __hfma2(h2tanh_apx(__hadd2(w2p[4*g+1], hu1)), vv1, a2);
            a2 = __hfma2(h2tanh_apx(__hadd2(w2p[4*g+2], hu2)), vv2, a2);
            a2 = __hfma2(h2tanh_apx(__hadd2(w2p[4*g+3], hu3)), vv3, a2);

            a3 = __hfma2(h2tanh_apx(__hadd2(w3p[4*g+0], hu0)), vv0, a3);
            a3 = __hfma2(h2tanh_apx(__hadd2(w3p[4*g+1], hu1)), vv1, a3);
            a3 = __hfma2(h2tanh_apx(__hadd2(w3p[4*g+2], hu2)), vv2, a3);
            a3 = __hfma2(h2tanh_apx(__hadd2(w3p[4*g+3], hu3)), vv3, a3);
        }
        float2 d0 = __half22float2(a0); f0.x += d0.x; f0.y += d0.y;
        float2 d1 = __half22float2(a1); f1.x += d1.x; f1.y += d1.y;
        float2 d2 = __half22float2(a2); f2.x += d2.x; f2.y += d2.y;
        float2 d3 = __half22float2(a3); f3.x += d3.x; f3.y += d3.y;
    }

    float* dst = g_scores + ((size_t)(b*LL + i0 + ib))*LL + j0 + jl;
    dst[0*LL] = f0.x + f0.y;
    dst[1*LL] = f1.x + f1.y;
    dst[2*LL] = f2.x + f2.y;
    dst[3*LL] = f3.x + f3.y;
}

// ------ Kernel 2: softmax + out. 8 rows/block, all-rows register blocking ------
__global__ void __launch_bounds__(512) softmax_out_kernel(const float* __restrict__ h,
                                                          float* __restrict__ out){
    __shared__ union SMU {
        struct { float p_s[SR][LL]; float p_t[LL][SR]; } a;  // 16KB + 16KB
        float4 part[8][SR][32];                              // 32KB (used after AV loop)
    } sm;
    __shared__ float inv_s[SR];

    int b  = blockIdx.y;
    int i0 = blockIdx.x * SR;
    int t  = threadIdx.x;

    // load 8x512 score rows
    const float4* src = (const float4*)(g_scores + ((size_t)(b*LL + i0))*LL);
    float4* ps4 = (float4*)&sm.a.p_s[0][0];
    ps4[t]       = src[t];
    ps4[t + 512] = src[t + 512];
    __syncthreads();

    int w = t >> 5, lane = t & 31;
    if (w < SR){
        int r = w;
        float m = -1e30f;
#pragma unroll
        for (int q = 0; q < 16; q++) m = fmaxf(m, sm.a.p_s[r][lane + q*32]);
#pragma unroll
        for (int o = 16; o; o >>= 1) m = fmaxf(m, __shfl_xor_sync(0xffffffffu, m, o));
        float sum = 0.f;
#pragma unroll
        for (int q = 0; q < 16; q++){
            int j = lane + q*32;
            float e = __expf(sm.a.p_s[r][j] - m);
            sm.a.p_t[j][r] = e;                 // transposed for AV
            sum += e;
        }
#pragma unroll
        for (int o = 16; o; o >>= 1) sum += __shfl_xor_sync(0xffffffffu, sum, o);
        if (lane == 0) inv_s[r] = 1.f / sum;
    }
    __syncthreads();

    // AV: thread = (d4:32) x (jc:16); each thread accumulates ALL 8 rows
    int d4 = t & 31;
    int jc = t >> 5;
    float4 acc[SR];
#pragma unroll
    for (int r = 0; r < SR; r++) acc[r] = make_float4(0.f,0.f,0.f,0.f);
    const float4* hp = (const float4*)(h + (size_t)b*LL*DD) + d4;
    int jbeg = jc * 32;

#pragma unroll 4
    for (int jj = 0; jj < 32; ++jj){
        int j = jbeg + jj;
        float4 hv = hp[(size_t)j*32];                          // feeds 32 FMA
        float4 p0 = *(const float4*)&sm.a.p_t[j][0];           // broadcast
        float4 p1 = *(const float4*)&sm.a.p_t[j][4];           // broadcast
        acc[0].x = fmaf(p0.x, hv.x, acc[0].x); acc[0].y = fmaf(p0.x, hv.y, acc[0].y);
        acc[0].z = fmaf(p0.x, hv.z, acc[0].z); acc[0].w = fmaf(p0.x, hv.w, acc[0].w);
        acc[1].x = fmaf(p0.y, hv.x, acc[1].x); acc[1].y = fmaf(p0.y, hv.y, acc[1].y);
        acc[1].z = fmaf(p0.y, hv.z, acc[1].z); acc[1].w = fmaf(p0.y, hv.w, acc[1].w);
        acc[2].x = fmaf(p0.z, hv.x, acc[2].x); acc[2].y = fmaf(p0.z, hv.y, acc[2].y);
        acc[2].z = fmaf(p0.z, hv.z, acc[2].z); acc[2].w = fmaf(p0.z, hv.w, acc[2].w);
        acc[3].x = fmaf(p0.w, hv.x, acc[3].x); acc[3].y = fmaf(p0.w, hv.y, acc[3].y);
        acc[3].z = fmaf(p0.w, hv.z, acc[3].z); acc[3].w = fmaf(p0.w, hv.w, acc[3].w);
        acc[4].x = fmaf(p1.x, hv.x, acc[4].x); acc[4].y = fmaf(p1.x, hv.y, acc[4].y);
        acc[4].z = fmaf(p1.x, hv.z, acc[4].z); acc[4].w = fmaf(p1.x, hv.w, acc[4].w);
        acc[5].x = fmaf(p1.y, hv.x, acc[5].x); acc[5].y = fmaf(p1.y, hv.y, acc[5].y);
        acc[5].z = fmaf(p1.y, hv.z, acc[5].z); acc[5].w = fmaf(p1.y, hv.w, acc[5].w);
        acc[6].x = fmaf(p1.z, hv.x, acc[6].x); acc[6].y = fmaf(p1.z, hv.y, acc[6].y);
        acc[6].z = fmaf(p1.z, hv.z, acc[6].z); acc[6].w = fmaf(p1.z, hv.w, acc[6].w);
        acc[7].x = fmaf(p1.w, hv.x, acc[7].x); acc[7].y = fmaf(p1.w, hv.y, acc[7].y);
        acc[7].z = fmaf(p1.w, hv.z, acc[7].z); acc[7].w = fmaf(p1.w, hv.w, acc[7].w);
    }
    __syncthreads();   // p_s/p_t dead; union region reused for partials

    if (jc >= 8){
#pragma unroll
        for (int r = 0; r < SR; r++) sm.part[jc-8][r][d4] = acc[r];
    }
    __syncthreads();
    if (jc < 8){
#pragma unroll
        for (int r = 0; r < SR; r++){
            float4 q = sm.part[jc][r][d4];
            acc[r].x += q.x; acc[r].y += q.y; acc[r].z += q.z; acc[r].w += q.w;
        }
    }
    __syncthreads();
    if (jc < 8){
#pragma unroll
        for (int r = 0; r < SR; r++) sm.part[jc][r][d4] = acc[r];
    }
    __syncthreads();

    if (t < 256){
        int rr = t >> 5, dd = t & 31;
        float4 o = make_float4(0.f,0.f,0.f,0.f);
#pragma unroll
        for (int q = 0; q < 8; q++){
            float4 p = sm.part[q][rr][dd];
            o.x += p.x; o.y += p.y; o.z += p.z; o.w += p.w;
        }
        float sc = inv_s[rr];
        o.x *= sc; o.y *= sc; o.z *= sc; o.w *= sc;
        ((float4*)(out + ((size_t)(b*LL + i0 + rr))*DD))[dd] = o;
    }
}

extern "C" void kernel_launch(void* const* d_in, const int* in_sizes, int n_in,
                              void* d_out, int out_size){
    const float* s = (const float*)d_in[0];
    const float* h = (const float*)d_in[1];
    const float* W = (const float*)d_in[2];
    const float* U = (const float*)d_in[3];
    const float* v = (const float*)d_in[4];
    float* out = (float*)d_out;

    proj_kernel<<<dim3((BB*LL)/PRT, 2), 256>>>(s, h, W, U);
    scores_kernel<<<dim3(LL/TJ, LL/TI, BB), 256>>>(v);
    softmax_out_kernel<<<dim3(LL/SR, BB), 512>>>(h, out);
}